// round 15
// baseline (speedup 1.0000x reference)
#include <cuda_runtime.h>
#include <cuda_bf16.h>
#include <stdint.h>

#define N_NODES  100000
#define N_EDGES  3200000
#define N_FEAT   128
#define HIDDEN   64
#define N_GRAPHS 256

#define BUCKET   128                         // fixed CSC bucket per node (max deg ~59)
#define NTB      ((N_NODES + 127) / 128)     // 782 mma row-tiles

// ---------------- device scratch ----------------
__device__ __align__(16) static __nv_bfloat162 g_P [N_NODES * 32];   // layer-1 messages (UNscaled)
__device__ __align__(16) static __nv_bfloat162 g_P2[N_NODES * 32];   // layer-2 messages (UNscaled)
__device__ __align__(16) static __nv_bfloat162 g_H1[N_NODES * 32];   // layer-1 out
__device__ __align__(16) static __nv_bfloat162 g_H2[N_NODES * 32];   // layer-2 out
__device__ __align__(16) static int   g_csc[N_NODES * BUCKET];       // 51.2MB bucketed CSC
__device__              static int   g_cursor[N_NODES];              // fill cursor == degree; zeroed by k_pool
__device__              static float g_dinv[N_NODES];

// ---------------- tensor-core GEMM body: P = A @ W (unscaled), bf16 out -----------
// mma.sync.aligned.m16n8k16.row.col.f32.bf16.bf16.f32
// Warp tile: 16 rows x 64 cols. A fragments straight from global.
// B staged in smem transposed [n][k], stride K+8 elems => conflict-free.

__device__ __forceinline__ unsigned cvt_pack_bf2(float hi, float lo) {
    unsigned r;
    asm("cvt.rn.bf16x2.f32 %0, %1, %2;" : "=r"(r) : "f"(hi), "f"(lo));
    return r;
}

__device__ __forceinline__ void mma16816(float* d, unsigned a0, unsigned a1,
                                         unsigned a2, unsigned a3,
                                         unsigned b0, unsigned b1) {
    asm("mma.sync.aligned.m16n8k16.row.col.f32.bf16.bf16.f32 "
        "{%0,%1,%2,%3}, {%4,%5,%6,%7}, {%8,%9}, {%0,%1,%2,%3};"
        : "+f"(d[0]), "+f"(d[1]), "+f"(d[2]), "+f"(d[3])
        : "r"(a0), "r"(a1), "r"(a2), "r"(a3), "r"(b0), "r"(b1));
}

template <int K, bool A_FP32>
__device__ __forceinline__ void mma_body(const void* __restrict__ Asrc,
                                         const float* __restrict__ W,
                                         __nv_bfloat162* __restrict__ Pout,
                                         __nv_bfloat16* sB,
                                         int tile0, int tstride) {
    constexpr int BSTRIDE = K + 8;                      // conflict-free LDS pattern

    for (int idx = threadIdx.x; idx < K * 64; idx += blockDim.x) {
        int k = idx >> 6, n = idx & 63;                 // W row-major [K][64]
        sB[n * BSTRIDE + k] = __float2bfloat16(W[idx]);
    }
    __syncthreads();

    int warp = threadIdx.x >> 5, lane = threadIdx.x & 31;
    int l4 = lane >> 2, lm = lane & 3;

    for (int tb = tile0; tb < NTB; tb += tstride) {
        int row0 = tb * 128 + warp * 16;
        int ra = row0 + l4;                             // rows for d0/d1
        int rb = ra + 8;                                // rows for d2/d3
        int ca = ra < N_NODES ? ra : N_NODES - 1;       // clamped load rows
        int cb = rb < N_NODES ? rb : N_NODES - 1;

        float acc[32];
        #pragma unroll
        for (int i = 0; i < 32; i++) acc[i] = 0.f;

        #pragma unroll
        for (int ks = 0; ks < K / 16; ks++) {
            int k0 = ks * 16 + lm * 2;
            unsigned a0, a1, a2, a3;
            if (A_FP32) {
                const float* X = (const float*)Asrc;
                float2 fa = *(const float2*)(X + (size_t)ca * K + k0);
                float2 fb = *(const float2*)(X + (size_t)cb * K + k0);
                float2 fc = *(const float2*)(X + (size_t)ca * K + k0 + 8);
                float2 fd = *(const float2*)(X + (size_t)cb * K + k0 + 8);
                a0 = cvt_pack_bf2(fa.y, fa.x);          // hi = k0+1, lo = k0
                a1 = cvt_pack_bf2(fb.y, fb.x);
                a2 = cvt_pack_bf2(fc.y, fc.x);
                a3 = cvt_pack_bf2(fd.y, fd.x);
            } else {
                const __nv_bfloat16* H = (const __nv_bfloat16*)Asrc;
                a0 = *(const unsigned*)(H + (size_t)ca * K + k0);
                a1 = *(const unsigned*)(H + (size_t)cb * K + k0);
                a2 = *(const unsigned*)(H + (size_t)ca * K + k0 + 8);
                a3 = *(const unsigned*)(H + (size_t)cb * K + k0 + 8);
            }
            #pragma unroll
            for (int nt = 0; nt < 8; nt++) {
                const __nv_bfloat16* bp = sB + (nt * 8 + l4) * BSTRIDE + k0;
                unsigned b0 = *(const unsigned*)bp;       // (k0,n),(k0+1,n)
                unsigned b1 = *(const unsigned*)(bp + 8); // (k0+8,n),(k0+9,n)
                mma16816(&acc[nt * 4], a0, a1, a2, a3, b0, b1);
            }
        }

        #pragma unroll
        for (int nt = 0; nt < 8; nt++) {
            int cp = nt * 4 + lm;                       // col-pair index (c0/2)
            if (ra < N_NODES)
                Pout[ra * 32 + cp] = __floats2bfloat162_rn(acc[nt*4+0], acc[nt*4+1]);
            if (rb < N_NODES)
                Pout[rb * 32 + cp] = __floats2bfloat162_rn(acc[nt*4+2], acc[nt*4+3]);
        }
    }
}

// ---------------- merged: bucketed CSC fill || layer-1 GEMM (role split) ----------
// Bucket fill needs only cursor==0 (guaranteed by previous call's k_pool);
// unscaled mma1 needs NOTHING graph-side. Zero dependency — both start at t=0.
// Role = bid % 5: 4 fill slots : 1 mma slot (work ratio 3125 : 782).
__global__ void k_fill_mma1(const int4* __restrict__ src4, const int4* __restrict__ dst4,
                            const float* __restrict__ X, const float* __restrict__ W1,
                            __nv_bfloat162* __restrict__ Pout) {
    __shared__ __nv_bfloat16 sB[64 * (N_FEAT + 8)];     // 17.4KB (mma role only)
    int grp = blockIdx.x / 5;
    int r   = blockIdx.x % 5;
    if (r < 4) {
        int i = (grp * 4 + r) * 256 + threadIdx.x;
        if (i < N_EDGES / 4) {
            int4 s = src4[i];
            int4 d = dst4[i];
            g_csc[d.x * BUCKET + atomicAdd(&g_cursor[d.x], 1)] = s.x;
            g_csc[d.y * BUCKET + atomicAdd(&g_cursor[d.y], 1)] = s.y;
            g_csc[d.z * BUCKET + atomicAdd(&g_cursor[d.z], 1)] = s.z;
            g_csc[d.w * BUCKET + atomicAdd(&g_cursor[d.w], 1)] = s.w;
        }
    } else {
        mma_body<N_FEAT, true>((const void*)X, W1, Pout, sB, grp, NTB);
    }
}

// ---------------- dinv from fill counts ----------------
__global__ void k_dinv() {
    int i = blockIdx.x * blockDim.x + threadIdx.x;
    if (i < N_NODES) g_dinv[i] = rsqrtf((float)(g_cursor[i] + 1));   // self-loop +1
}

// ---------------- standalone tensor-core GEMM (layer 2) ----------------
template <int K, bool A_FP32>
__global__ void k_mma(const void* __restrict__ Asrc, const float* __restrict__ W,
                      __nv_bfloat162* __restrict__ Pout) {
    __shared__ __nv_bfloat16 sB[64 * (K + 8)];
    mma_body<K, A_FP32>(Asrc, W, Pout, sB, blockIdx.x, gridDim.x);
}

// ---------------- gather core: acc = dinv[n]*P[n] + sum dinv[s]*P[s] --------------
// Unscaled messages; per-neighbor dinv folded into FMA (same instr count as FADD).
// dinv loads are warp-uniform broadcasts on a 400KB array -> L1-resident.
__device__ __forceinline__ float2 gather_node(const __nv_bfloat162* __restrict__ P,
                                              int n, int lane) {
    int deg = g_cursor[n];
    const int* bkt = g_csc + n * BUCKET;
    float dn = g_dinv[n];
    float2 self = __bfloat1622float2(P[n * 32 + lane]);
    float2 acc = make_float2(self.x * dn, self.y * dn);
    for (int p = 0; p < deg; p += 8) {
        int4 sa = *reinterpret_cast<const int4*>(bkt + p);
        int4 sb = *reinterpret_cast<const int4*>(bkt + p + 4);
        float ds0 = g_dinv[sa.x], ds1 = g_dinv[sa.y], ds2 = g_dinv[sa.z], ds3 = g_dinv[sa.w];
        float ds4 = g_dinv[sb.x], ds5 = g_dinv[sb.y], ds6 = g_dinv[sb.z], ds7 = g_dinv[sb.w];
        float2 v0 = __bfloat1622float2(P[(size_t)sa.x * 32 + lane]);
        float2 v1 = __bfloat1622float2(P[(size_t)sa.y * 32 + lane]);
        float2 v2 = __bfloat1622float2(P[(size_t)sa.z * 32 + lane]);
        float2 v3 = __bfloat1622float2(P[(size_t)sa.w * 32 + lane]);
        float2 v4 = __bfloat1622float2(P[(size_t)sb.x * 32 + lane]);
        float2 v5 = __bfloat1622float2(P[(size_t)sb.y * 32 + lane]);
        float2 v6 = __bfloat1622float2(P[(size_t)sb.z * 32 + lane]);
        float2 v7 = __bfloat1622float2(P[(size_t)sb.w * 32 + lane]);
        int rem = deg - p;
        acc.x = fmaf(ds0, v0.x, acc.x); acc.y = fmaf(ds0, v0.y, acc.y);
        if (rem > 1) { acc.x = fmaf(ds1, v1.x, acc.x); acc.y = fmaf(ds1, v1.y, acc.y); }
        if (rem > 2) { acc.x = fmaf(ds2, v2.x, acc.x); acc.y = fmaf(ds2, v2.y, acc.y); }
        if (rem > 3) { acc.x = fmaf(ds3, v3.x, acc.x); acc.y = fmaf(ds3, v3.y, acc.y); }
        if (rem > 4) { acc.x = fmaf(ds4, v4.x, acc.x); acc.y = fmaf(ds4, v4.y, acc.y); }
        if (rem > 5) { acc.x = fmaf(ds5, v5.x, acc.x); acc.y = fmaf(ds5, v5.y, acc.y); }
        if (rem > 6) { acc.x = fmaf(ds6, v6.x, acc.x); acc.y = fmaf(ds6, v6.y, acc.y); }
        if (rem > 7) { acc.x = fmaf(ds7, v7.x, acc.x); acc.y = fmaf(ds7, v7.y, acc.y); }
    }
    return acc;
}

// ---------------- gather layers ----------------
template <int RELU>
__global__ void k_gather(const __nv_bfloat162* __restrict__ P,
                         __nv_bfloat162* __restrict__ Hout,
                         const float* __restrict__ bias) {
    int widx = (blockIdx.x * blockDim.x + threadIdx.x) >> 5;
    if (widx >= N_NODES) return;
    int lane = threadIdx.x & 31;
    float2 b = reinterpret_cast<const float2*>(bias)[lane];
    float dn = g_dinv[widx];
    float2 acc = gather_node(P, widx, lane);
    float ox = dn * acc.x + b.x;
    float oy = dn * acc.y + b.y;
    if (RELU) { ox = fmaxf(ox, 0.f); oy = fmaxf(oy, 0.f); }
    Hout[widx * 32 + lane] = __floats2bfloat162_rn(ox, oy);
}

// ---------------- pool (mean per graph, bf16 in) + final linear + cleanup ---------
__device__ __forceinline__ int lbound(const int* __restrict__ a, int n, int key) {
    int lo = 0, hi = n;
    while (lo < hi) {
        int m = (lo + hi) >> 1;
        if (a[m] < key) lo = m + 1; else hi = m;
    }
    return lo;
}

__global__ void k_pool(const int* __restrict__ batch,
                       const float* __restrict__ Wl, const float* __restrict__ bl,
                       float* __restrict__ out) {
    __shared__ float2 sm[256];               // 8 partitions x 32 col-pairs
    int g = blockIdx.x;
    int t = threadIdx.x;                     // 256 threads
    int lo = lbound(batch, N_NODES, g);
    int hi = lbound(batch, N_NODES, g + 1);

    int cp   = t & 31;
    int part = t >> 5;
    float2 s = make_float2(0.f, 0.f);
    for (int n = lo + part; n < hi; n += 8) {
        float2 v = __bfloat1622float2(g_H2[(size_t)n * 32 + cp]);
        s.x += v.x; s.y += v.y;
    }
    sm[t] = s;
    __syncthreads();
    if (t < 32) {
        float2 v = sm[t];
        #pragma unroll
        for (int p = 1; p < 8; p++) {
            float2 u = sm[t + 32 * p];
            v.x += u.x; v.y += u.y;
        }
        int cnt = hi - lo;
        float inv = 1.f / (float)(cnt > 0 ? cnt : 1);
        float2 w = reinterpret_cast<const float2*>(Wl)[t];
        sm[t] = make_float2(v.x * inv * w.x + v.y * inv * w.y, 0.f);
    }
    __syncthreads();
    if (t == 0) {
        float r = 0.f;
        #pragma unroll
        for (int c = 0; c < 32; c++) r += sm[c].x;
        out[g] = r + bl[0];
    }
    // cleanup: zero cursor for next call (stream-serialized; zero-init covers call 1)
    for (int i = g * 256 + t; i < N_NODES; i += N_GRAPHS * 256) g_cursor[i] = 0;
}

// ---------------- launch: 6 kernels, single stream ----------------
extern "C" void kernel_launch(void* const* d_in, const int* in_sizes, int n_in,
                              void* d_out, int out_size) {
    const float* x     = (const float*)d_in[0];
    const int*   eidx  = (const int*)d_in[1];
    const int*   batch = (const int*)d_in[2];
    const float* W1    = (const float*)d_in[3];
    const float* b1    = (const float*)d_in[4];
    const float* W2    = (const float*)d_in[5];
    const float* b2    = (const float*)d_in[6];
    const float* Wl    = (const float*)d_in[7];
    const float* bl    = (const float*)d_in[8];
    float* out = (float*)d_out;

    const int4* src4 = (const int4*)eidx;
    const int4* dst4 = (const int4*)(eidx + N_EDGES);

    __nv_bfloat162* H1v; cudaGetSymbolAddress((void**)&H1v, g_H1);
    __nv_bfloat162* H2v; cudaGetSymbolAddress((void**)&H2v, g_H2);
    __nv_bfloat162* Pv;  cudaGetSymbolAddress((void**)&Pv,  g_P);
    __nv_bfloat162* P2v; cudaGetSymbolAddress((void**)&P2v, g_P2);

    // 1) bucketed CSC fill || layer-1 GEMM (no prior passes needed)
    k_fill_mma1<<<NTB * 5, 256>>>(src4, dst4, x, W1, Pv);

    // 2) dinv from fill counts
    k_dinv<<<(N_NODES + 255) / 256, 256>>>();

    // 3) layer 1 gather (per-neighbor dinv FMA, relu)
    k_gather<1><<<(N_NODES * 32 + 255) / 256, 256>>>(Pv, H1v, b1);

    // 4) layer 2 GEMM (H1 bf16 direct, unscaled)
    k_mma<HIDDEN, false><<<NTB, 256>>>((const void*)H1v, W2, P2v);

    // 5) layer 2 gather
    k_gather<0><<<(N_NODES * 32 + 255) / 256, 256>>>(P2v, H2v, b2);

    // 6) pool + head (+ cursor cleanup for next call)
    k_pool<<<N_GRAPHS, 256>>>(batch, Wl, bl, out);
}

// round 16
// speedup vs baseline: 1.6268x; 1.6268x over previous
#include <cuda_runtime.h>
#include <cuda_bf16.h>
#include <stdint.h>

#define N_NODES  100000
#define N_EDGES  3200000
#define N_FEAT   128
#define HIDDEN   64
#define N_GRAPHS 256

// Padded CSC capacity: E + 3 per node + 8 slack for unroll-8 overread
#define CSC_CAP  (N_EDGES + 4 * N_NODES + 8)
#define NTB      ((N_NODES + 127) / 128)    // 782 mma row-tiles

#define SCAN_B   1024
#define SCAN_NB  ((N_NODES + SCAN_B - 1) / SCAN_B)   // 98 blocks, all wave-1 resident
#define AGG_FLAG 0x40000000

// ---------------- device scratch ----------------
__device__ __align__(16) static __nv_bfloat162 g_P [N_NODES * 32];  // layer-1 messages
__device__ __align__(16) static __nv_bfloat162 g_P2[N_NODES * 32];  // layer-2 messages
__device__ __align__(16) static __nv_bfloat162 g_H1[N_NODES * 32];  // layer-1 out
__device__ __align__(16) static __nv_bfloat162 g_H2[N_NODES * 32];  // layer-2 out
__device__ __align__(16) static int   g_csc[CSC_CAP];               // compact CSC; pad slots stay 0
__device__              static int   g_deg[N_NODES];                // zeroed by k_pool each call
__device__              static int   g_rowptr[N_NODES];
__device__              static int   g_cursor[N_NODES];
__device__              static float g_dinv[N_NODES];
__device__              static int   g_agg[SCAN_NB];                // scan aggregates+flag; zeroed by k_pool

// ---------------- degree histogram, 4 edges/thread ----------------
// g_deg==0 at entry: zero-init at load; k_pool restores it at the end of every call.
__global__ void k_count(const int4* __restrict__ dst4) {
    int i = blockIdx.x * blockDim.x + threadIdx.x;
    if (i < N_EDGES / 4) {
        int4 d = dst4[i];
        atomicAdd(&g_deg[d.x], 1);
        atomicAdd(&g_deg[d.y], 1);
        atomicAdd(&g_deg[d.z], 1);
        atomicAdd(&g_deg[d.w], 1);
    }
}

// ---------------- single-pass exclusive scan of padded degrees (+ dinv) -----------
// Aggregate-only lookback: block publishes its aggregate (flagged) immediately,
// then warp 0 spin-sums predecessors' aggregates. 98 blocks <= 148 SMs => all
// resident wave-1, publishers always make progress (publish in warp 31, spin in
// warp 0, no __syncthreads in between).
__global__ void __launch_bounds__(SCAN_B) k_scan() {
    __shared__ int smi[33];
    __shared__ int soff_sh;
    int t = threadIdx.x;
    int lane = t & 31, w = t >> 5;
    int c = blockIdx.x;
    int i = c * SCAN_B + t;

    int v = 0;
    if (i < N_NODES) {
        int d = g_deg[i];
        g_dinv[i] = rsqrtf((float)(d + 1));          // fused dinv (self-loop +1)
        v = (d + 3) & ~3;                            // pad segment to multiple of 4
    }
    int inc = v;
    #pragma unroll
    for (int o = 1; o < 32; o <<= 1) {
        int u = __shfl_up_sync(0xFFFFFFFFu, inc, o);
        if (lane >= o) inc += u;
    }
    if (lane == 31) smi[w] = inc;                    // 32 warp sums
    __syncthreads();
    if (t < 32) {
        int s = smi[t];
        int inc2 = s;
        #pragma unroll
        for (int o = 1; o < 32; o <<= 1) {
            int u = __shfl_up_sync(0xFFFFFFFFu, inc2, o);
            if (t >= o) inc2 += u;
        }
        smi[t] = inc2 - s;                           // exclusive warp offsets
    }
    __syncthreads();
    int excl = (inc - v) + smi[w];                   // block-local exclusive

    // publish aggregate (warp 31) — no sync between this and the lookback spin
    if (t == SCAN_B - 1)
        atomicExch(&g_agg[c], (excl + v) | AGG_FLAG);

    // lookback (warp 0): sum predecessors' aggregates
    if (t < 32) {
        int s = 0;
        for (int j = t; j < c; j += 32) {
            int a;
            while (((a = atomicAdd(&g_agg[j], 0)) & AGG_FLAG) == 0) __nanosleep(32);
            s += a & ~AGG_FLAG;
        }
        #pragma unroll
        for (int o = 16; o; o >>= 1) s += __shfl_down_sync(0xFFFFFFFFu, s, o);
        if (t == 0) soff_sh = s;
    }
    __syncthreads();
    if (i < N_NODES) {
        int r = excl + soff_sh;
        g_rowptr[i] = r;
        g_cursor[i] = r;
    }
}

// ---------------- tensor-core GEMM body: P = (A @ W) * dinv, bf16 out -------------
__device__ __forceinline__ unsigned cvt_pack_bf2(float hi, float lo) {
    unsigned r;
    asm("cvt.rn.bf16x2.f32 %0, %1, %2;" : "=r"(r) : "f"(hi), "f"(lo));
    return r;
}

__device__ __forceinline__ void mma16816(float* d, unsigned a0, unsigned a1,
                                         unsigned a2, unsigned a3,
                                         unsigned b0, unsigned b1) {
    asm("mma.sync.aligned.m16n8k16.row.col.f32.bf16.bf16.f32 "
        "{%0,%1,%2,%3}, {%4,%5,%6,%7}, {%8,%9}, {%0,%1,%2,%3};"
        : "+f"(d[0]), "+f"(d[1]), "+f"(d[2]), "+f"(d[3])
        : "r"(a0), "r"(a1), "r"(a2), "r"(a3), "r"(b0), "r"(b1));
}

template <int K, bool A_FP32>
__device__ __forceinline__ void mma_body(const void* __restrict__ Asrc,
                                         const float* __restrict__ W,
                                         __nv_bfloat162* __restrict__ Pout,
                                         __nv_bfloat16* sB,
                                         int tile0, int tstride) {
    constexpr int BSTRIDE = K + 8;                      // conflict-free LDS pattern

    for (int idx = threadIdx.x; idx < K * 64; idx += blockDim.x) {
        int k = idx >> 6, n = idx & 63;                 // W row-major [K][64]
        sB[n * BSTRIDE + k] = __float2bfloat16(W[idx]);
    }
    __syncthreads();

    int warp = threadIdx.x >> 5, lane = threadIdx.x & 31;
    int l4 = lane >> 2, lm = lane & 3;

    for (int tb = tile0; tb < NTB; tb += tstride) {
        int row0 = tb * 128 + warp * 16;
        int ra = row0 + l4;                             // rows for d0/d1
        int rb = ra + 8;                                // rows for d2/d3
        int ca = ra < N_NODES ? ra : N_NODES - 1;       // clamped load rows
        int cb = rb < N_NODES ? rb : N_NODES - 1;

        float acc[32];
        #pragma unroll
        for (int i = 0; i < 32; i++) acc[i] = 0.f;

        #pragma unroll
        for (int ks = 0; ks < K / 16; ks++) {
            int k0 = ks * 16 + lm * 2;
            unsigned a0, a1, a2, a3;
            if (A_FP32) {
                const float* X = (const float*)Asrc;
                float2 fa = *(const float2*)(X + (size_t)ca * K + k0);
                float2 fb = *(const float2*)(X + (size_t)cb * K + k0);
                float2 fc = *(const float2*)(X + (size_t)ca * K + k0 + 8);
                float2 fd = *(const float2*)(X + (size_t)cb * K + k0 + 8);
                a0 = cvt_pack_bf2(fa.y, fa.x);          // hi = k0+1, lo = k0
                a1 = cvt_pack_bf2(fb.y, fb.x);
                a2 = cvt_pack_bf2(fc.y, fc.x);
                a3 = cvt_pack_bf2(fd.y, fd.x);
            } else {
                const __nv_bfloat16* H = (const __nv_bfloat16*)Asrc;
                a0 = *(const unsigned*)(H + (size_t)ca * K + k0);
                a1 = *(const unsigned*)(H + (size_t)cb * K + k0);
                a2 = *(const unsigned*)(H + (size_t)ca * K + k0 + 8);
                a3 = *(const unsigned*)(H + (size_t)cb * K + k0 + 8);
            }
            #pragma unroll
            for (int nt = 0; nt < 8; nt++) {
                const __nv_bfloat16* bp = sB + (nt * 8 + l4) * BSTRIDE + k0;
                unsigned b0 = *(const unsigned*)bp;       // (k0,n),(k0+1,n)
                unsigned b1 = *(const unsigned*)(bp + 8); // (k0+8,n),(k0+9,n)
                mma16816(&acc[nt * 4], a0, a1, a2, a3, b0, b1);
            }
        }

        float da = g_dinv[ca], db = g_dinv[cb];
        #pragma unroll
        for (int nt = 0; nt < 8; nt++) {
            int cp = nt * 4 + lm;                       // col-pair index (c0/2)
            if (ra < N_NODES)
                Pout[ra * 32 + cp] = __floats2bfloat162_rn(acc[nt*4+0]*da, acc[nt*4+1]*da);
            if (rb < N_NODES)
                Pout[rb * 32 + cp] = __floats2bfloat162_rn(acc[nt*4+2]*db, acc[nt*4+3]*db);
        }
    }
}

// ---------------- merged: CSC fill || layer-1 GEMM (role split, no barrier) -------
// After k_scan both are runnable: fill needs g_cursor, mma1 needs g_dinv only.
// Role = bid % 5: 4 fill slots : 1 mma slot (work ratio 3125 : 782).
__global__ void k_fill_mma1(const int4* __restrict__ src4, const int4* __restrict__ dst4,
                            const float* __restrict__ X, const float* __restrict__ W1,
                            __nv_bfloat162* __restrict__ Pout) {
    __shared__ __nv_bfloat16 sB[64 * (N_FEAT + 8)];     // 17.4KB (mma role only)
    int grp = blockIdx.x / 5;
    int r   = blockIdx.x % 5;
    if (r < 4) {
        int i = (grp * 4 + r) * 256 + threadIdx.x;
        if (i < N_EDGES / 4) {
            int4 s = src4[i];
            int4 d = dst4[i];
            g_csc[atomicAdd(&g_cursor[d.x], 1)] = s.x;
            g_csc[atomicAdd(&g_cursor[d.y], 1)] = s.y;
            g_csc[atomicAdd(&g_cursor[d.z], 1)] = s.z;
            g_csc[atomicAdd(&g_cursor[d.w], 1)] = s.w;
        }
    } else {
        mma_body<N_FEAT, true>((const void*)X, W1, Pout, sB, grp, NTB);
    }
}

// ---------------- standalone tensor-core GEMM (layer 2) ----------------
template <int K, bool A_FP32>
__global__ void k_mma(const void* __restrict__ Asrc, const float* __restrict__ W,
                      __nv_bfloat162* __restrict__ Pout) {
    __shared__ __nv_bfloat16 sB[64 * (K + 8)];
    mma_body<K, A_FP32>(Asrc, W, Pout, sB, blockIdx.x, gridDim.x);
}

// ---------------- gather-sum aggregation (bf16 messages, fp32 accumulate) ---------
template <int RELU>
__global__ void k_gather(const __nv_bfloat162* __restrict__ P,
                         __nv_bfloat162* __restrict__ Hout,
                         const float* __restrict__ bias) {
    int widx = (blockIdx.x * blockDim.x + threadIdx.x) >> 5;
    if (widx >= N_NODES) return;
    int lane = threadIdx.x & 31;

    float dn = g_dinv[widx];
    int start = g_rowptr[widx];
    int end = start + g_deg[widx];

    float2 acc = __bfloat1622float2(P[widx * 32 + lane]);   // self term

    for (int p = start; p < end; p += 8) {
        int4 sa = *reinterpret_cast<const int4*>(g_csc + p);
        int4 sb = *reinterpret_cast<const int4*>(g_csc + p + 4);
        float2 v0 = __bfloat1622float2(P[(size_t)sa.x * 32 + lane]);
        float2 v1 = __bfloat1622float2(P[(size_t)sa.y * 32 + lane]);
        float2 v2 = __bfloat1622float2(P[(size_t)sa.z * 32 + lane]);
        float2 v3 = __bfloat1622float2(P[(size_t)sa.w * 32 + lane]);
        float2 v4 = __bfloat1622float2(P[(size_t)sb.x * 32 + lane]);
        float2 v5 = __bfloat1622float2(P[(size_t)sb.y * 32 + lane]);
        float2 v6 = __bfloat1622float2(P[(size_t)sb.z * 32 + lane]);
        float2 v7 = __bfloat1622float2(P[(size_t)sb.w * 32 + lane]);
        int rem = end - p;
        acc.x += v0.x; acc.y += v0.y;
        if (rem > 1) { acc.x += v1.x; acc.y += v1.y; }
        if (rem > 2) { acc.x += v2.x; acc.y += v2.y; }
        if (rem > 3) { acc.x += v3.x; acc.y += v3.y; }
        if (rem > 4) { acc.x += v4.x; acc.y += v4.y; }
        if (rem > 5) { acc.x += v5.x; acc.y += v5.y; }
        if (rem > 6) { acc.x += v6.x; acc.y += v6.y; }
        if (rem > 7) { acc.x += v7.x; acc.y += v7.y; }
    }

    float2 b = reinterpret_cast<const float2*>(bias)[lane];
    float ox = dn * acc.x + b.x;
    float oy = dn * acc.y + b.y;
    if (RELU) { ox = fmaxf(ox, 0.f); oy = fmaxf(oy, 0.f); }
    Hout[widx * 32 + lane] = __floats2bfloat162_rn(ox, oy);
}

// ---------------- pool (mean per graph, bf16 in) + final linear + cleanup ---------
__device__ __forceinline__ int lbound(const int* __restrict__ a, int n, int key) {
    int lo = 0, hi = n;
    while (lo < hi) {
        int m = (lo + hi) >> 1;
        if (a[m] < key) lo = m + 1; else hi = m;
    }
    return lo;
}

__global__ void k_pool(const int* __restrict__ batch,
                       const float* __restrict__ Wl, const float* __restrict__ bl,
                       float* __restrict__ out) {
    __shared__ float2 sm[256];               // 8 partitions x 32 col-pairs
    int g = blockIdx.x;
    int t = threadIdx.x;                     // 256 threads
    int lo = lbound(batch, N_NODES, g);
    int hi = lbound(batch, N_NODES, g + 1);

    int cp   = t & 31;
    int part = t >> 5;
    float2 s = make_float2(0.f, 0.f);
    for (int n = lo + part; n < hi; n += 8) {
        float2 v = __bfloat1622float2(g_H2[(size_t)n * 32 + cp]);
        s.x += v.x; s.y += v.y;
    }
    sm[t] = s;
    __syncthreads();
    if (t < 32) {
        float2 v = sm[t];
        #pragma unroll
        for (int p = 1; p < 8; p++) {
            float2 u = sm[t + 32 * p];
            v.x += u.x; v.y += u.y;
        }
        int cnt = hi - lo;
        float inv = 1.f / (float)(cnt > 0 ? cnt : 1);
        float2 w = reinterpret_cast<const float2*>(Wl)[t];
        sm[t] = make_float2(v.x * inv * w.x + v.y * inv * w.y, 0.f);
    }
    __syncthreads();
    if (t == 0) {
        float r = 0.f;
        #pragma unroll
        for (int c = 0; c < 32; c++) r += sm[c].x;
        out[g] = r + bl[0];
    }
    // cleanup for next call (stream-serialized; zero-init covers the first call)
    for (int i = g * 256 + t; i < N_NODES; i += N_GRAPHS * 256) g_deg[i] = 0;
    if (g == 0 && t < SCAN_NB) g_agg[t] = 0;
}

// ---------------- launch: 7 kernels, single stream ----------------
extern "C" void kernel_launch(void* const* d_in, const int* in_sizes, int n_in,
                              void* d_out, int out_size) {
    const float* x     = (const float*)d_in[0];
    const int*   eidx  = (const int*)d_in[1];
    const int*   batch = (const int*)d_in[2];
    const float* W1    = (const float*)d_in[3];
    const float* b1    = (const float*)d_in[4];
    const float* W2    = (const float*)d_in[5];
    const float* b2    = (const float*)d_in[6];
    const float* Wl    = (const float*)d_in[7];
    const float* bl    = (const float*)d_in[8];
    float* out = (float*)d_out;

    const int4* src4 = (const int4*)eidx;
    const int4* dst4 = (const int4*)(eidx + N_EDGES);

    __nv_bfloat162* H1v; cudaGetSymbolAddress((void**)&H1v, g_H1);
    __nv_bfloat162* H2v; cudaGetSymbolAddress((void**)&H2v, g_H2);
    __nv_bfloat162* Pv;  cudaGetSymbolAddress((void**)&Pv,  g_P);
    __nv_bfloat162* P2v; cudaGetSymbolAddress((void**)&P2v, g_P2);

    int nThreads = 256;
    int nbEdge4 = (N_EDGES / 4 + nThreads - 1) / nThreads;

    // --- CSC build prefix: count (g_deg pre-zeroed by previous call's k_pool),
    //     then single-pass scan (dinv + rowptr + cursor) ---
    k_count<<<nbEdge4, nThreads>>>(dst4);
    k_scan<<<SCAN_NB, SCAN_B>>>();

    // --- CSC fill || layer-1 GEMM (role-split, no dependency between them) ---
    k_fill_mma1<<<NTB * 5, 256>>>(src4, dst4, x, W1, Pv);

    // --- layer 1 gather ---
    k_gather<1><<<(N_NODES * 32 + 255) / 256, 256>>>(Pv, H1v, b1);

    // --- layer 2: tensor-core GEMM (H1 bf16 direct) + gather ---
    k_mma<HIDDEN, false><<<NTB, 256>>>((const void*)H1v, W2, P2v);
    k_gather<0><<<(N_NODES * 32 + 255) / 256, 256>>>(P2v, H2v, b2);

    // --- pool + head (+ cleanup of g_deg / g_agg for the next call) ---
    k_pool<<<N_GRAPHS, 256>>>(batch, Wl, bl, out);
}